// round 10
// baseline (speedup 1.0000x reference)
#include <cuda_runtime.h>
#include <cstdint>

#define BT   64
#define P    68
#define NTHR 256
typedef unsigned long long ull;

// ---------------- persistent device scratch ----------------
// All weight panels are stored PRE-DUPLICATED: each value w appears as (w,w)
// so GEMM B-operands are direct LDS.128 f32x2 broadcasts (no MOV, no remat).
__device__ __align__(16) float g_W1T[784*128];   // [k][j] plain (phase 1)
__device__ __align__(16) float g_L1Pd[65536];    // 16 slots: [8k][128c dup] -M1T | U1T
__device__ __align__(16) float g_W22d[24576];    // 192k x 64c dup (W2T ; -M2T stacked)
__device__ __align__(16) float g_U2d[8192];      // 64k x 64c dup
__device__ __align__(16) float g_L3d[8192];      // W3T 64k x 32c dup | -M3T 32k dup | U3T 32k dup
__device__ __align__(16) float g_c1[128];
__device__ __align__(16) float g_c2[64];
__device__ __align__(16) float g_c3[32];
__device__ __align__(16) float g_XW[65536*128];  // xw, column-major per 64-row tile

// ---------------- helpers ----------------
__device__ __forceinline__ ull dup2(float x) {
    ull r; asm("mov.b64 %0, {%1, %1};" : "=l"(r) : "f"(x)); return r;
}
__device__ __forceinline__ void up2(ull v, float &lo, float &hi) {
    asm("mov.b64 {%0, %1}, %2;" : "=f"(lo), "=f"(hi) : "l"(v));
}
__device__ __forceinline__ void fma2(ull &d, ull a, ull b) {
    asm("fma.rn.f32x2 %0, %1, %2, %0;" : "+l"(d) : "l"(a), "l"(b));
}
// tanh(x) = 1 - 2/(1+e^{2x})  via MUFU.EX2 + MUFU.RCP (~1e-6 abs err)
__device__ __forceinline__ float ftanh(float x) {
    float e, r;
    asm("ex2.approx.ftz.f32 %0, %1;" : "=f"(e) : "f"(x * 2.8853900817779268f));
    asm("rcp.approx.ftz.f32 %0, %1;" : "=f"(r) : "f"(e + 1.0f));
    return fmaf(-2.0f, r, 1.0f);
}

// L1 dual GEMM vs dup'd panel, K=8. Thread: rows i0..i0+7 (4 genuine pairs)
// x cols j4..j4+3 per matrix. Panel layout: k*256 + h*128 + cq*4 (+2048 for U).
__device__ __forceinline__ void gemmL1d(const float* __restrict__ A,
                                        const float* __restrict__ Bd,
                                        int i0, int cq,
                                        ull (&m)[4][4], ull (&u)[4][4]) {
#pragma unroll
    for (int k = 0; k < 8; k++) {
        ulonglong2 a01 = *reinterpret_cast<const ulonglong2*>(A + k * P + i0);
        ulonglong2 a23 = *reinterpret_cast<const ulonglong2*>(A + k * P + i0 + 4);
        const float* b = Bd + k * 256 + cq * 4;
        ulonglong2 bm0 = *reinterpret_cast<const ulonglong2*>(b);
        ulonglong2 bm1 = *reinterpret_cast<const ulonglong2*>(b + 128);
        ulonglong2 bu0 = *reinterpret_cast<const ulonglong2*>(b + 2048);
        ulonglong2 bu1 = *reinterpret_cast<const ulonglong2*>(b + 2176);
        ull ap[4] = {a01.x, a01.y, a23.x, a23.y};
        ull bm[4] = {bm0.x, bm0.y, bm1.x, bm1.y};
        ull bu[4] = {bu0.x, bu0.y, bu1.x, bu1.y};
#pragma unroll
        for (int p = 0; p < 4; p++) {
#pragma unroll
            for (int c = 0; c < 4; c++) {
                fma2(m[p][c], ap[p], bm[c]);
                fma2(u[p][c], ap[p], bu[c]);
            }
        }
    }
}

// L2-style GEMM vs dup'd panel, K=32. Thread: 4 row pairs x 2 cols (j2, j2+1).
__device__ __forceinline__ void gemmA2d(const float* __restrict__ A,
                                        const float* __restrict__ Bd,
                                        int i0, int j2, ull (&acc)[4][2]) {
#pragma unroll 8
    for (int k = 0; k < 32; k++) {
        ulonglong2 a01 = *reinterpret_cast<const ulonglong2*>(A + k * P + i0);
        ulonglong2 a23 = *reinterpret_cast<const ulonglong2*>(A + k * P + i0 + 4);
        ulonglong2 b = *reinterpret_cast<const ulonglong2*>(Bd + k * 128 + j2 * 2);
        ull ap[4] = {a01.x, a01.y, a23.x, a23.y};
#pragma unroll
        for (int p = 0; p < 4; p++) {
            fma2(acc[p][0], ap[p], b.x);
            fma2(acc[p][1], ap[p], b.y);
        }
    }
}

// L3-style GEMM vs dup'd panel (64 floats per k). Thread: 2 row pairs x 2 cols.
template<int K>
__device__ __forceinline__ void gemmA3d(const float* __restrict__ A,
                                        const float* __restrict__ Bd,
                                        int i03, int j3, ull (&acc)[2][2]) {
#pragma unroll 8
    for (int k = 0; k < K; k++) {
        ulonglong2 a = *reinterpret_cast<const ulonglong2*>(A + k * P + i03);
        ulonglong2 b = *reinterpret_cast<const ulonglong2*>(Bd + k * 64 + j3 * 2);
        fma2(acc[0][0], a.x, b.x);
        fma2(acc[0][1], a.x, b.y);
        fma2(acc[1][0], a.y, b.x);
        fma2(acc[1][1], a.y, b.y);
    }
}

// 4096-float panel staging: 4 float4 per thread
__device__ __forceinline__ void pld4(const float* __restrict__ src, int tid, float4 (&r)[4]) {
#pragma unroll
    for (int j = 0; j < 4; j++)
        r[j] = *reinterpret_cast<const float4*>(src + j * 1024 + tid * 4);
}
__device__ __forceinline__ void pst4(float* dst, int tid, const float4 (&r)[4]) {
#pragma unroll
    for (int j = 0; j < 4; j++)
        *reinterpret_cast<float4*>(dst + j * 1024 + tid * 4) = r[j];
}

// dup'd index helpers (c = output column, d = 0/1 dup half)
__device__ __forceinline__ int idxL1(int k, int c) {     // within one 2048-float matrix part
    return (k & 7) * 256 + ((c >> 1) & 1) * 128 + (c >> 2) * 4 + (c & 1) * 2;
}
__device__ __forceinline__ int idx64(int k, int c) {     // 64-col dup row (128 fl per k)
    return k * 128 + (c >> 1) * 4 + (c & 1) * 2;
}
__device__ __forceinline__ int idx32(int k, int c) {     // 32-col dup row (64 fl per k)
    return k * 64 + (c >> 1) * 4 + (c & 1) * 2;
}

// ---------------- prep kernel ----------------
__global__ void prep_all(const float* __restrict__ W1w, const float* __restrict__ W1b,
                         const float* __restrict__ U1w,
                         const float* __restrict__ W2w, const float* __restrict__ W2b,
                         const float* __restrict__ U2w,
                         const float* __restrict__ W3w, const float* __restrict__ W3b,
                         const float* __restrict__ U3w,
                         const float* __restrict__ fb3w, const float* __restrict__ fb3b,
                         const float* __restrict__ fb2w, const float* __restrict__ fb2b,
                         const float* __restrict__ fb1w, const float* __restrict__ fb1b) {
    __shared__ float row_s[784];
    __shared__ float red_s[128];
    const int bid = blockIdx.x;
    const int tid = threadIdx.x;   // 128

    if (bid < 128) {
        const int j = bid;         // output col of M1T
        for (int d = tid; d < 784; d += 128) row_s[d] = W1w[j * 784 + d];
        __syncthreads();
        {
            const int k = tid;
            float s = 0.f;
#pragma unroll 4
            for (int d = 0; d < 784; d++) s += row_s[d] * fb1w[d * 128 + k];
            int base = (k >> 3) * 4096 + idxL1(k, j);
            g_L1Pd[base] = -s;
            g_L1Pd[base + 1] = -s;
        }
        float ps = 0.f;
        for (int d = tid; d < 784; d += 128) ps += row_s[d] * fb1b[d];
        red_s[tid] = ps;
        __syncthreads();
        for (int off = 64; off > 0; off >>= 1) {
            if (tid < off) red_s[tid] += red_s[tid + off];
            __syncthreads();
        }
        if (tid == 0) g_c1[j] = W1b[j] - red_s[0];
    } else if (bid < 192) {
        const int j = bid - 128;
        for (int d = tid; d < 128; d += 128) row_s[d] = W2w[j * 128 + d];
        __syncthreads();
        if (tid < 64) {
            const int k = tid;
            float s = 0.f;
#pragma unroll 4
            for (int d = 0; d < 128; d++) s += row_s[d] * fb2w[d * 64 + k];
            int base = idx64(128 + k, j);
            g_W22d[base] = -s;
            g_W22d[base + 1] = -s;
        }
        float ps = 0.f;
        for (int d = tid; d < 128; d += 128) ps += row_s[d] * fb2b[d];
        red_s[tid] = ps;
        __syncthreads();
        for (int off = 64; off > 0; off >>= 1) {
            if (tid < off) red_s[tid] += red_s[tid + off];
            __syncthreads();
        }
        if (tid == 0) g_c2[j] = W2b[j] - red_s[0];
    } else if (bid < 224) {
        const int j = bid - 192;
        for (int d = tid; d < 64; d += 128) row_s[d] = W3w[j * 64 + d];
        __syncthreads();
        if (tid < 32) {
            const int k = tid;
            float s = 0.f;
#pragma unroll 4
            for (int d = 0; d < 64; d++) s += row_s[d] * fb3w[d * 32 + k];
            int base = 4096 + idx32(k, j);
            g_L3d[base] = -s;
            g_L3d[base + 1] = -s;
        }
        float ps = 0.f;
        for (int d = tid; d < 64; d += 128) ps += row_s[d] * fb3b[d];
        red_s[tid] = ps;
        __syncthreads();
        for (int off = 64; off > 0; off >>= 1) {
            if (tid < off) red_s[tid] += red_s[tid + off];
            __syncthreads();
        }
        if (tid == 0) g_c3[j] = W3b[j] - red_s[0];
    } else {
        const int idx0 = (bid - 224) * 128 + tid;
        const int stride = 32 * 128;
        for (int t = idx0; t < 784 * 128; t += stride) {          // W1T plain
            int k = t >> 7, j = t & 127;
            g_W1T[t] = W1w[j * 784 + k];
        }
        for (int t = idx0; t < 128 * 128; t += stride) {          // U1T dup
            int k = t >> 7, j = t & 127;
            float v = U1w[j * 128 + k];
            int base = (k >> 3) * 4096 + 2048 + idxL1(k, j);
            g_L1Pd[base] = v;
            g_L1Pd[base + 1] = v;
        }
        for (int t = idx0; t < 128 * 64; t += stride) {           // W2T dup
            int k = t >> 6, j = t & 63;
            float v = W2w[j * 128 + k];
            int base = idx64(k, j);
            g_W22d[base] = v;
            g_W22d[base + 1] = v;
        }
        for (int t = idx0; t < 64 * 64; t += stride) {            // U2T dup
            int k = t >> 6, j = t & 63;
            float v = U2w[j * 64 + k];
            int base = idx64(k, j);
            g_U2d[base] = v;
            g_U2d[base + 1] = v;
        }
        for (int t = idx0; t < 64 * 32; t += stride) {            // W3T dup
            int k = t >> 5, j = t & 31;
            float v = W3w[j * 64 + k];
            int base = idx32(k, j);
            g_L3d[base] = v;
            g_L3d[base + 1] = v;
        }
        for (int t = idx0; t < 32 * 32; t += stride) {            // U3T dup
            int k = t >> 5, j = t & 31;
            float v = U3w[j * 32 + k];
            int base = 6144 + idx32(k, j);
            g_L3d[base] = v;
            g_L3d[base + 1] = v;
        }
    }
}

// ---------------- main kernel ----------------
// smem floats (23744 = 94976 B, 2 CTAs/SM):
//   h1s[128*68]@0  h2s[64*68]@8704  h3s[32*68]@13056   (states end 15232)
//   buf0@15232(4096)  buf1@19328(4096)  sB@23424(320)
// phase-1 overlay: xck@0 [64][116]=7424, wck@7424 [112][128] (ends 21760).
// buf0/buf1 filled AFTER phase 1; sB (@23424) beyond the overlay.
__global__ void __launch_bounds__(NTHR, 2)
pcnet_main(const float* __restrict__ x,
           const float* __restrict__ U1b, const float* __restrict__ U2b,
           const float* __restrict__ U3b,
           const float* __restrict__ clfw, const float* __restrict__ clfb,
           const int* __restrict__ steps_p,
           float* __restrict__ out) {
    extern __shared__ float sm[];
    float* h1s  = sm;
    float* h2s  = sm + 8704;
    float* h3s  = sm + 13056;
    float* buf0 = sm + 15232;
    float* buf1 = sm + 19328;
    float* sB   = sm + 23424;
    float* xck  = sm;           // overlay
    float* wck  = sm + 7424;    // overlay

    const int tid  = threadIdx.x;
    const int row0 = blockIdx.x * BT;
    float* const xwg = g_XW + (size_t)blockIdx.x * 8192;   // [128 cols][64 rows]

    const int wid  = tid >> 5, lane = tid & 31;
    // L1/L2 mapping: warp = 4 row-groups x 8 col-groups
    const int rg   = ((wid & 1) << 2) + (lane >> 3);   // 0..7
    const int cq   = ((wid >> 1) << 3) + (lane & 7);   // 0..31
    const int i0   = rg * 8;       // 8 rows = 4 genuine pairs
    const int j4   = cq * 4;       // L1 cols j4..j4+3
    const int j2   = cq * 2;       // L2 cols j2, j2+1
    // L3 mapping
    const int rg3  = ((wid & 3) << 2) + (lane >> 3);   // 0..15
    const int cq3  = ((wid >> 2) << 3) + (lane & 7);   // 0..15
    const int i03  = rg3 * 4;      // 4 rows = 2 pairs
    const int j3   = cq3 * 2;      // L3 cols j3, j3+1

    int steps = *steps_p;
    if (steps < 0 || steps > 64) steps = 5;

    // stage biases (region beyond phase-1 overlay)
    for (int t = tid; t < 320; t += NTHR) {
        float v;
        if (t < 32) v = g_c3[t];
        else if (t < 64) v = U3b[t - 32];
        else if (t < 128) v = g_c2[t - 64];
        else if (t < 192) v = U2b[t - 128];
        else v = U1b[t - 192];
        sB[t] = v;
    }

    // ---- phase 1: xw = x @ W1^T + c1 -> g_XW (column-major per tile) ----
    {
        const int p_i0 = (tid >> 4) * 4;
        const int p_j4 = (tid & 15) * 4;
        ull axw[4][4] = {};
        for (int c = 0; c < 7; c++) {
            for (int idx = tid; idx < 64 * 28; idx += NTHR) {
                int r = idx / 28, k4 = idx - r * 28;
                *reinterpret_cast<float4*>(xck + r * 116 + k4 * 4) =
                    *reinterpret_cast<const float4*>(x + (size_t)(row0 + r) * 784 + c * 112 + k4 * 4);
            }
            for (int idx = tid; idx < 112 * 32; idx += NTHR) {
                int kk = idx >> 5, jj = idx & 31;
                *reinterpret_cast<float4*>(wck + kk * 128 + jj * 4) =
                    *reinterpret_cast<const float4*>(g_W1T + (size_t)(c * 112 + kk) * 128 + jj * 4);
            }
            __syncthreads();
#pragma unroll 2
            for (int kk = 0; kk < 112; kk++) {
                ulonglong2 b0 = *reinterpret_cast<const ulonglong2*>(wck + kk * 128 + p_j4);
                ulonglong2 b1 = *reinterpret_cast<const ulonglong2*>(wck + kk * 128 + 64 + p_j4);
                ull Ar[4] = {dup2(xck[(p_i0 + 0) * 116 + kk]), dup2(xck[(p_i0 + 1) * 116 + kk]),
                             dup2(xck[(p_i0 + 2) * 116 + kk]), dup2(xck[(p_i0 + 3) * 116 + kk])};
#pragma unroll
                for (int r = 0; r < 4; r++) {
                    fma2(axw[r][0], Ar[r], b0.x);
                    fma2(axw[r][1], Ar[r], b0.y);
                    fma2(axw[r][2], Ar[r], b1.x);
                    fma2(axw[r][3], Ar[r], b1.y);
                }
            }
            __syncthreads();
        }
        float c1v[8];
#pragma unroll
        for (int t = 0; t < 4; t++) { c1v[t] = g_c1[p_j4 + t]; c1v[4 + t] = g_c1[64 + p_j4 + t]; }
#pragma unroll
        for (int c = 0; c < 4; c++) {
            int col = (c < 2) ? (p_j4 + 2 * c) : (60 + p_j4 + 2 * c);
            float4 v0, v1;
#pragma unroll
            for (int r = 0; r < 4; r++) {
                float lo, hi;
                up2(axw[r][c], lo, hi);
                if (r == 0) { v0.x = lo + c1v[2 * c]; v1.x = hi + c1v[2 * c + 1]; }
                else if (r == 1) { v0.y = lo + c1v[2 * c]; v1.y = hi + c1v[2 * c + 1]; }
                else if (r == 2) { v0.z = lo + c1v[2 * c]; v1.z = hi + c1v[2 * c + 1]; }
                else { v0.w = lo + c1v[2 * c]; v1.w = hi + c1v[2 * c + 1]; }
            }
            *reinterpret_cast<float4*>(xwg + col * 64 + p_i0)       = v0;
            *reinterpret_cast<float4*>(xwg + (col + 1) * 64 + p_i0) = v1;
        }
    }
    __syncthreads();
    // zero states, preload first panel (L3d slot A)
    for (int i = tid; i < 15232; i += NTHR) sm[i] = 0.f;
    for (int idx = tid; idx < 1024; idx += NTHR)
        *reinterpret_cast<float4*>(buf0 + idx * 4) = *reinterpret_cast<const float4*>(g_L3d + idx * 4);
    __syncthreads();

    float* cur = buf0;
    float* oth = buf1;

    // ---- step loop: 26 dup-panel slots ----
    for (int s = 0; s < steps; s++) {
        float4 pr[4];

        // slot 0: L3a = W3T dup (A = h2s, K=64)
        ull aA3[2][2] = {}, aU3[2][2] = {};
        pld4(g_L3d + 4096, tid, pr);
        gemmA3d<64>(h2s, cur, i03, j3, aA3);
        pst4(oth, tid, pr); __syncthreads();
        { float* t = cur; cur = oth; oth = t; }

        // slot 1: L3b = -M3T dup | U3T dup (A = h3s, K=32 each)
        pld4(g_W22d, tid, pr);
        gemmA3d<32>(h3s, cur, i03, j3, aA3);
        gemmA3d<32>(h3s, cur + 2048, i03, j3, aU3);
        pst4(oth, tid, pr); __syncthreads();
        { float* t = cur; cur = oth; oth = t; }

        // ---- update h3 ----
        {
            float4 h0 = *reinterpret_cast<float4*>(h3s + j3 * P + i03);
            float4 h1v = *reinterpret_cast<float4*>(h3s + (j3 + 1) * P + i03);
            float cc0 = sB[j3], cc1 = sB[j3 + 1];
            float ub0 = sB[32 + j3], ub1 = sB[32 + j3 + 1];
            float a0, a1, a2, a3, u0, u1, u2, u3;
            up2(aA3[0][0], a0, a1); up2(aA3[1][0], a2, a3);
            up2(aU3[0][0], u0, u1); up2(aU3[1][0], u2, u3);
            h0.x += ftanh(a0 + cc0) + ftanh(u0 + ub0);
            h0.y += ftanh(a1 + cc0) + ftanh(u1 + ub0);
            h0.z += ftanh(a2 + cc0) + ftanh(u2 + ub0);
            h0.w += ftanh(a3 + cc0) + ftanh(u3 + ub0);
            up2(aA3[0][1], a0, a1); up2(aA3[1][1], a2, a3);
            up2(aU3[0][1], u0, u1); up2(aU3[1][1], u2, u3);
            h1v.x += ftanh(a0 + cc1) + ftanh(u0 + ub1);
            h1v.y += ftanh(a1 + cc1) + ftanh(u1 + ub1);
            h1v.z += ftanh(a2 + cc1) + ftanh(u2 + ub1);
            h1v.w += ftanh(a3 + cc1) + ftanh(u3 + ub1);
            *reinterpret_cast<float4*>(h3s + j3 * P + i03) = h0;
            *reinterpret_cast<float4*>(h3s + (j3 + 1) * P + i03) = h1v;
        }

        // slots 2-7: stacked [h1;h2] @ [W2T;-M2T] dup, K=32 per slot
        ull aA2[4][2] = {};
#pragma unroll 1
        for (int p = 0; p < 6; p++) {
            const float* Ap = (p < 4) ? (h1s + 32 * p * P) : (h2s + 32 * (p - 4) * P);
            const float* nx = (p < 5) ? (g_W22d + (p + 1) * 4096) : g_U2d;
            pld4(nx, tid, pr);
            gemmA2d(Ap, cur, i0, j2, aA2);
            pst4(oth, tid, pr); __syncthreads();
            float* t = cur; cur = oth; oth = t;
        }
        // slots 8-9: U2T dup (A = h2s)
        ull aU2[4][2] = {};
#pragma unroll 1
        for (int p = 0; p < 2; p++) {
            const float* nx = p ? g_L1Pd : (g_U2d + 4096);
            pld4(nx, tid, pr);
            gemmA2d(h2s + 32 * p * P, cur, i0, j2, aU2);
            pst4(oth, tid, pr); __syncthreads();
            float* t = cur; cur = oth; oth = t;
        }

        // ---- update h2 ----
#pragma unroll
        for (int c = 0; c < 2; c++) {
            int col = j2 + c;
            float cc = sB[64 + col], ub = sB[128 + col];
            float4 v0 = *reinterpret_cast<float4*>(h2s + col * P + i0);
            float4 v1 = *reinterpret_cast<float4*>(h2s + col * P + i0 + 4);
            float a0, a1, a2, a3, a4, a5, a6, a7;
            float u0, u1, u2, u3, u4, u5, u6, u7;
            up2(aA2[0][c], a0, a1); up2(aA2[1][c], a2, a3);
            up2(aA2[2][c], a4, a5); up2(aA2[3][c], a6, a7);
            up2(aU2[0][c], u0, u1); up2(aU2[1][c], u2, u3);
            up2(aU2[2][c], u4, u5); up2(aU2[3][c], u6, u7);
            v0.x += ftanh(a0 + cc) + ftanh(u0 + ub);
            v0.y += ftanh(a1 + cc) + ftanh(u1 + ub);
            v0.z += ftanh(a2 + cc) + ftanh(u2 + ub);
            v0.w += ftanh(a3 + cc) + ftanh(u3 + ub);
            v1.x += ftanh(a4 + cc) + ftanh(u4 + ub);
            v1.y += ftanh(a5 + cc) + ftanh(u5 + ub);
            v1.z += ftanh(a6 + cc) + ftanh(u6 + ub);
            v1.w += ftanh(a7 + cc) + ftanh(u7 + ub);
            *reinterpret_cast<float4*>(h2s + col * P + i0)     = v0;
            *reinterpret_cast<float4*>(h2s + col * P + i0 + 4) = v1;
        }

        // slots 10-25: L1 dup pair-panels (-M1T | U1T), K=8 each
        ull aM1[4][4] = {}, aU1[4][4] = {};
#pragma unroll 1
        for (int p = 0; p < 16; p++) {
            const float* nx = (p < 15) ? (g_L1Pd + (p + 1) * 4096) : g_L3d;
            pld4(nx, tid, pr);
            gemmL1d(h1s + 8 * p * P, cur, i0, cq, aM1, aU1);
            pst4(oth, tid, pr); __syncthreads();
            float* t = cur; cur = oth; oth = t;
        }

        // ---- update h1 (xw from L2-resident g_XW, column-major) ----
#pragma unroll
        for (int c = 0; c < 4; c++) {
            int col = j4 + c;
            float ub = sB[192 + col];
            float4 x0 = *reinterpret_cast<const float4*>(xwg + col * 64 + i0);
            float4 x1 = *reinterpret_cast<const float4*>(xwg + col * 64 + i0 + 4);
            float4 v0 = *reinterpret_cast<float4*>(h1s + col * P + i0);
            float4 v1 = *reinterpret_cast<float4*>(h1s + col * P + i0 + 4);
            float m0, m1, m2, m3, m4, m5, m6, m7;
            float u0, u1, u2, u3, u4, u5, u6, u7;
            up2(aM1[0][c], m0, m1); up2(aM1[1][c], m2, m3);
            up2(aM1[2][c], m4, m5); up2(aM1[3][c], m6, m7);
            up2(aU1[0][c], u0, u1); up2(aU1[1][c], u2, u3);
            up2(aU1[2][c], u4, u5); up2(aU1[3][c], u6, u7);
            v0.x += ftanh(x0.x + m0) + ftanh(u0 + ub);
            v0.y += ftanh(x0.y + m1) + ftanh(u1 + ub);
            v0.z += ftanh(x0.z + m2) + ftanh(u2 + ub);
            v0.w += ftanh(x0.w + m3) + ftanh(u3 + ub);
            v1.x += ftanh(x1.x + m4) + ftanh(u4 + ub);
            v1.y += ftanh(x1.y + m5) + ftanh(u5 + ub);
            v1.z += ftanh(x1.z + m6) + ftanh(u6 + ub);
            v1.w += ftanh(x1.w + m7) + ftanh(u7 + ub);
            *reinterpret_cast<float4*>(h1s + col * P + i0)     = v0;
            *reinterpret_cast<float4*>(h1s + col * P + i0 + 4) = v1;
        }
        // h1 writes ordered before next step's first h1s read (slot 2) by the
        // next step's slot-0/slot-1 barriers; h2/h3 writes covered likewise.
    }
    __syncthreads();

    // ---- classifier: out = h3 @ clf^T + clf_b ----
    for (int idx = tid; idx < BT * 10; idx += NTHR) {
        int r = idx / 10, cc = idx - r * 10;
        float sacc = clfb[cc];
#pragma unroll
        for (int k = 0; k < 32; k++) sacc += h3s[k * P + r] * clfw[cc * 32 + k];
        out[(size_t)(row0 + r) * 10 + cc] = sacc;
    }
}

// ---------------- launch ----------------
extern "C" void kernel_launch(void* const* d_in, const int* in_sizes, int n_in,
                              void* d_out, int out_size) {
    const float* x    = (const float*)d_in[0];
    const float* W1w  = (const float*)d_in[1];
    const float* W1b  = (const float*)d_in[2];
    const float* U1w  = (const float*)d_in[3];
    const float* U1b  = (const float*)d_in[4];
    const float* W2w  = (const float*)d_in[5];
    const float* W2b  = (const float*)d_in[6];
    const float* U2w  = (const float*)d_in[7];
    const float* U2b  = (const float*)d_in[8];
    const float* W3w  = (const float*)d_in[9];
    const float* W3b  = (const float*)d_in[10];
    const float* U3w  = (const float*)d_in[11];
    const float* U3b  = (const float*)d_in[12];
    const float* fb3w = (const float*)d_in[13];
    const float* fb3b = (const float*)d_in[14];
    const float* fb2w = (const float*)d_in[15];
    const float* fb2b = (const float*)d_in[16];
    const float* fb1w = (const float*)d_in[17];
    const float* fb1b = (const float*)d_in[18];
    const float* clfw = (const float*)d_in[19];
    const float* clfb = (const float*)d_in[20];
    const int*   stp  = (const int*)d_in[21];

    int B = in_sizes[0] / 784;
    if (B > 65536) B = 65536;   // g_XW capacity guard

    prep_all<<<256, 128>>>(W1w, W1b, U1w, W2w, W2b, U2w, W3w, W3b, U3w,
                           fb3w, fb3b, fb2w, fb2b, fb1w, fb1b);

    const int smem_bytes = 23744 * 4;   // 94976 -> 2 CTAs/SM
    cudaFuncSetAttribute(pcnet_main, cudaFuncAttributeMaxDynamicSharedMemorySize, smem_bytes);
    pcnet_main<<<B / BT, NTHR, smem_bytes>>>(x, U1b, U2b, U3b, clfw, clfb, stp, (float*)d_out);
}

// round 11
// speedup vs baseline: 1.1476x; 1.1476x over previous
#include <cuda_runtime.h>
#include <cstdint>

#define BT   64
#define P    68
#define NTHR 256
typedef unsigned long long ull;

// ---------------- persistent device scratch ----------------
__device__ __align__(16) float g_W1T[784*128];   // [k][j] (phase 1)
__device__ __align__(16) float g_PA[40960];      // 8 slots x 16k x [ -M1T(128) | U1T(128) | W2T(64) ]
__device__ __align__(16) float g_PB[10240];      // 2 slots x 32k x [ -M2T(64)  | U2T(64)  | W3T(32) ]
__device__ __align__(16) float g_PC[2048];       // 32k x [ -M3T(32) | U3T(32) ]
__device__ __align__(16) float g_c1[128];
__device__ __align__(16) float g_c2[64];
__device__ __align__(16) float g_c3[32];
__device__ __align__(16) float g_XW[65536*128];  // xw, column-major per 64-row tile

// ---------------- helpers ----------------
__device__ __forceinline__ ull dup2(float x) {
    ull r; asm("mov.b64 %0, {%1, %1};" : "=l"(r) : "f"(x)); return r;
}
__device__ __forceinline__ void up2(ull v, float &lo, float &hi) {
    asm("mov.b64 {%0, %1}, %2;" : "=f"(lo), "=f"(hi) : "l"(v));
}
__device__ __forceinline__ void fma2(ull &d, ull a, ull b) {
    asm("fma.rn.f32x2 %0, %1, %2, %0;" : "+l"(d) : "l"(a), "l"(b));
}
// tanh(x) = 1 - 2/(1+e^{2x})  via MUFU.EX2 + MUFU.RCP (~1e-6 abs err)
__device__ __forceinline__ float ftanh(float x) {
    float e, r;
    asm("ex2.approx.ftz.f32 %0, %1;" : "=f"(e) : "f"(x * 2.8853900817779268f));
    asm("rcp.approx.ftz.f32 %0, %1;" : "=f"(r) : "f"(e + 1.0f));
    return fmaf(-2.0f, r, 1.0f);
}
__device__ __forceinline__ void addf4(float4 &v, int r, float d) {
    if (r == 0) v.x += d; else if (r == 1) v.y += d;
    else if (r == 2) v.z += d; else v.w += d;
}

// ---- fused loop A: A=h1 chunk (K=16), B-panel row = [M1T|U1T|W2T] (320 fl/k)
__device__ __forceinline__ void gemmA(const float* __restrict__ A,
                                      const float* __restrict__ Bp,
                                      int i0, int j4, int j2,
                                      ull (&m)[8][2], ull (&u)[8][2], ull (&w)[8]) {
#pragma unroll 8
    for (int kk = 0; kk < 16; kk++) {
        float4 a0 = *reinterpret_cast<const float4*>(A + kk * P + i0);
        float4 a1 = *reinterpret_cast<const float4*>(A + kk * P + i0 + 4);
        const float* br = Bp + kk * 320;
        ulonglong2 bM = *reinterpret_cast<const ulonglong2*>(br + j4);
        ulonglong2 bU = *reinterpret_cast<const ulonglong2*>(br + 128 + j4);
        ull bW = *reinterpret_cast<const ull*>(br + 256 + j2);
        ull Ar[8] = {dup2(a0.x), dup2(a0.y), dup2(a0.z), dup2(a0.w),
                     dup2(a1.x), dup2(a1.y), dup2(a1.z), dup2(a1.w)};
#pragma unroll
        for (int r = 0; r < 8; r++) {
            fma2(m[r][0], Ar[r], bM.x);
            fma2(m[r][1], Ar[r], bM.y);
            fma2(u[r][0], Ar[r], bU.x);
            fma2(u[r][1], Ar[r], bU.y);
            fma2(w[r], Ar[r], bW);
        }
    }
}

// ---- fused loop B: A=h2 chunk (K=32), B-panel row = [M2T|U2T|W3T] (160 fl/k)
__device__ __forceinline__ void gemmB(const float* __restrict__ A,
                                      const float* __restrict__ Bp,
                                      int i0, int j2, int jc,
                                      ull (&m)[8], ull (&u)[8], ull (&w)[8]) {
#pragma unroll 8
    for (int kk = 0; kk < 32; kk++) {
        float4 a0 = *reinterpret_cast<const float4*>(A + kk * P + i0);
        float4 a1 = *reinterpret_cast<const float4*>(A + kk * P + i0 + 4);
        const float* br = Bp + kk * 160;
        ull bM = *reinterpret_cast<const ull*>(br + j2);
        ull bU = *reinterpret_cast<const ull*>(br + 64 + j2);
        ull bW = *reinterpret_cast<const ull*>(br + 128 + jc);
        ull Ar[8] = {dup2(a0.x), dup2(a0.y), dup2(a0.z), dup2(a0.w),
                     dup2(a1.x), dup2(a1.y), dup2(a1.z), dup2(a1.w)};
#pragma unroll
        for (int r = 0; r < 8; r++) {
            fma2(m[r], Ar[r], bM);
            fma2(u[r], Ar[r], bU);
            fma2(w[r], Ar[r], bW);
        }
    }
}

// ---- fused loop C: A=h3 (K=32), B-panel row = [M3T|U3T] (64 fl/k)
__device__ __forceinline__ void gemmC(const float* __restrict__ A,
                                      const float* __restrict__ Bp,
                                      int i0, int jc, ull (&m)[8], ull (&u)[8]) {
#pragma unroll 8
    for (int kk = 0; kk < 32; kk++) {
        float4 a0 = *reinterpret_cast<const float4*>(A + kk * P + i0);
        float4 a1 = *reinterpret_cast<const float4*>(A + kk * P + i0 + 4);
        const float* br = Bp + kk * 64;
        ull bM = *reinterpret_cast<const ull*>(br + jc);
        ull bU = *reinterpret_cast<const ull*>(br + 32 + jc);
        ull Ar[8] = {dup2(a0.x), dup2(a0.y), dup2(a0.z), dup2(a0.w),
                     dup2(a1.x), dup2(a1.y), dup2(a1.z), dup2(a1.w)};
#pragma unroll
        for (int r = 0; r < 8; r++) {
            fma2(m[r], Ar[r], bM);
            fma2(u[r], Ar[r], bU);
        }
    }
}

// 5120-float panel staging: 5 float4 per thread
__device__ __forceinline__ void pld5(const float* __restrict__ src, int tid, float4 (&r)[5]) {
#pragma unroll
    for (int j = 0; j < 5; j++)
        r[j] = *reinterpret_cast<const float4*>(src + j * 1024 + tid * 4);
}
__device__ __forceinline__ void pst5(float* dst, int tid, const float4 (&r)[5]) {
#pragma unroll
    for (int j = 0; j < 5; j++)
        *reinterpret_cast<float4*>(dst + j * 1024 + tid * 4) = r[j];
}

// ---------------- prep kernel ----------------
__global__ void prep_all(const float* __restrict__ W1w, const float* __restrict__ W1b,
                         const float* __restrict__ U1w,
                         const float* __restrict__ W2w, const float* __restrict__ W2b,
                         const float* __restrict__ U2w,
                         const float* __restrict__ W3w, const float* __restrict__ W3b,
                         const float* __restrict__ U3w,
                         const float* __restrict__ fb3w, const float* __restrict__ fb3b,
                         const float* __restrict__ fb2w, const float* __restrict__ fb2b,
                         const float* __restrict__ fb1w, const float* __restrict__ fb1b) {
    __shared__ float row_s[784];
    __shared__ float red_s[128];
    const int bid = blockIdx.x;
    const int tid = threadIdx.x;   // 128

    if (bid < 128) {
        const int j = bid;
        for (int d = tid; d < 784; d += 128) row_s[d] = W1w[j * 784 + d];
        __syncthreads();
        {
            const int k = tid;
            float s = 0.f;
#pragma unroll 4
            for (int d = 0; d < 784; d++) s += row_s[d] * fb1w[d * 128 + k];
            g_PA[(k >> 4) * 5120 + (k & 15) * 320 + j] = -s;   // -M1T
        }
        float ps = 0.f;
        for (int d = tid; d < 784; d += 128) ps += row_s[d] * fb1b[d];
        red_s[tid] = ps;
        __syncthreads();
        for (int off = 64; off > 0; off >>= 1) {
            if (tid < off) red_s[tid] += red_s[tid + off];
            __syncthreads();
        }
        if (tid == 0) g_c1[j] = W1b[j] - red_s[0];
    } else if (bid < 192) {
        const int j = bid - 128;
        for (int d = tid; d < 128; d += 128) row_s[d] = W2w[j * 128 + d];
        __syncthreads();
        if (tid < 64) {
            const int k = tid;
            float s = 0.f;
#pragma unroll 4
            for (int d = 0; d < 128; d++) s += row_s[d] * fb2w[d * 64 + k];
            g_PB[(k >> 5) * 5120 + (k & 31) * 160 + j] = -s;   // -M2T
        }
        float ps = 0.f;
        for (int d = tid; d < 128; d += 128) ps += row_s[d] * fb2b[d];
        red_s[tid] = ps;
        __syncthreads();
        for (int off = 64; off > 0; off >>= 1) {
            if (tid < off) red_s[tid] += red_s[tid + off];
            __syncthreads();
        }
        if (tid == 0) g_c2[j] = W2b[j] - red_s[0];
    } else if (bid < 224) {
        const int j = bid - 192;
        for (int d = tid; d < 64; d += 128) row_s[d] = W3w[j * 64 + d];
        __syncthreads();
        if (tid < 32) {
            const int k = tid;
            float s = 0.f;
#pragma unroll 4
            for (int d = 0; d < 64; d++) s += row_s[d] * fb3w[d * 32 + k];
            g_PC[k * 64 + j] = -s;                              // -M3T
        }
        float ps = 0.f;
        for (int d = tid; d < 64; d += 128) ps += row_s[d] * fb3b[d];
        red_s[tid] = ps;
        __syncthreads();
        for (int off = 64; off > 0; off >>= 1) {
            if (tid < off) red_s[tid] += red_s[tid + off];
            __syncthreads();
        }
        if (tid == 0) g_c3[j] = W3b[j] - red_s[0];
    } else {
        const int idx0 = (bid - 224) * 128 + tid;
        const int stride = 32 * 128;
        for (int t = idx0; t < 784 * 128; t += stride) {          // W1T plain
            int k = t >> 7, j = t & 127;
            g_W1T[t] = W1w[j * 784 + k];
        }
        for (int t = idx0; t < 128 * 128; t += stride) {          // U1T into PA
            int k = t >> 7, j = t & 127;
            g_PA[(k >> 4) * 5120 + (k & 15) * 320 + 128 + j] = U1w[j * 128 + k];
        }
        for (int t = idx0; t < 128 * 64; t += stride) {           // W2T into PA
            int k = t >> 6, j = t & 63;
            g_PA[(k >> 4) * 5120 + (k & 15) * 320 + 256 + j] = W2w[j * 128 + k];
        }
        for (int t = idx0; t < 64 * 64; t += stride) {            // U2T into PB
            int k = t >> 6, j = t & 63;
            g_PB[(k >> 5) * 5120 + (k & 31) * 160 + 64 + j] = U2w[j * 64 + k];
        }
        for (int t = idx0; t < 64 * 32; t += stride) {            // W3T into PB
            int k = t >> 5, j = t & 31;
            g_PB[(k >> 5) * 5120 + (k & 31) * 160 + 128 + j] = W3w[j * 64 + k];
        }
        for (int t = idx0; t < 32 * 32; t += stride) {            // U3T into PC
            int k = t >> 5, j = t & 31;
            g_PC[k * 64 + 32 + j] = U3w[j * 32 + k];
        }
    }
}

// ---------------- main kernel ----------------
// smem floats (25792 = 103168 B, 2 CTAs/SM):
//   h1s[128*68]@0  h2s[64*68]@8704  h3s[32*68]@13056  (states end 15232)
//   buf0@15232(5120)  buf1@20352(5120)  sB@25472(320)
// phase-1 overlay: xck@0 [64][116]=7424, wck@7424 [112][128] (ends 21760 < sB).
// bufs are filled only AFTER phase 1.
__global__ void __launch_bounds__(NTHR, 2)
pcnet_main(const float* __restrict__ x,
           const float* __restrict__ U1b, const float* __restrict__ U2b,
           const float* __restrict__ U3b,
           const float* __restrict__ clfw, const float* __restrict__ clfb,
           const int* __restrict__ steps_p,
           float* __restrict__ out) {
    extern __shared__ float sm[];
    float* h1s  = sm;
    float* h2s  = sm + 8704;
    float* h3s  = sm + 13056;
    float* buf0 = sm + 15232;
    float* buf1 = sm + 20352;
    float* sB   = sm + 25472;
    float* xck  = sm;           // overlay
    float* wck  = sm + 7424;    // overlay

    const int tid  = threadIdx.x;
    const int row0 = blockIdx.x * BT;
    float* const xwg = g_XW + (size_t)blockIdx.x * 8192;   // [128 cols][64 rows]

    const int wid  = tid >> 5, lane = tid & 31;
    const int rg   = ((wid & 1) << 2) + (lane >> 3);   // 0..7
    const int cq   = ((wid >> 1) << 3) + (lane & 7);   // 0..31
    const int i0   = rg * 8;
    const int j4   = cq * 4;          // L1 cols
    const int j2   = cq * 2;          // L2 cols
    const int jc   = (cq & 15) * 2;   // L3 cols (halves redundant)

    int steps = *steps_p;
    if (steps < 0 || steps > 64) steps = 5;

    // stage biases (beyond phase-1 overlay)
    for (int t = tid; t < 320; t += NTHR) {
        float v;
        if (t < 32) v = g_c3[t];
        else if (t < 64) v = U3b[t - 32];
        else if (t < 128) v = g_c2[t - 64];
        else if (t < 192) v = U2b[t - 128];
        else v = U1b[t - 192];
        sB[t] = v;
    }

    // ---- phase 1: xw = x @ W1^T + c1 -> g_XW (column-major per tile) ----
    {
        const int p_i0 = (tid >> 4) * 4;
        const int p_j4 = (tid & 15) * 4;
        ull axw[4][4] = {};
        for (int c = 0; c < 7; c++) {
            for (int idx = tid; idx < 64 * 28; idx += NTHR) {
                int r = idx / 28, k4 = idx - r * 28;
                *reinterpret_cast<float4*>(xck + r * 116 + k4 * 4) =
                    *reinterpret_cast<const float4*>(x + (size_t)(row0 + r) * 784 + c * 112 + k4 * 4);
            }
            for (int idx = tid; idx < 112 * 32; idx += NTHR) {
                int kk = idx >> 5, jj = idx & 31;
                *reinterpret_cast<float4*>(wck + kk * 128 + jj * 4) =
                    *reinterpret_cast<const float4*>(g_W1T + (size_t)(c * 112 + kk) * 128 + jj * 4);
            }
            __syncthreads();
#pragma unroll 2
            for (int kk = 0; kk < 112; kk++) {
                ulonglong2 b0 = *reinterpret_cast<const ulonglong2*>(wck + kk * 128 + p_j4);
                ulonglong2 b1 = *reinterpret_cast<const ulonglong2*>(wck + kk * 128 + 64 + p_j4);
                ull Ar[4] = {dup2(xck[(p_i0 + 0) * 116 + kk]), dup2(xck[(p_i0 + 1) * 116 + kk]),
                             dup2(xck[(p_i0 + 2) * 116 + kk]), dup2(xck[(p_i0 + 3) * 116 + kk])};
#pragma unroll
                for (int r = 0; r < 4; r++) {
                    fma2(axw[r][0], Ar[r], b0.x);
                    fma2(axw[r][1], Ar[r], b0.y);
                    fma2(axw[r][2], Ar[r], b1.x);
                    fma2(axw[r][3], Ar[r], b1.y);
                }
            }
            __syncthreads();
        }
        float c1v[8];
#pragma unroll
        for (int t = 0; t < 4; t++) { c1v[t] = g_c1[p_j4 + t]; c1v[4 + t] = g_c1[64 + p_j4 + t]; }
#pragma unroll
        for (int c = 0; c < 4; c++) {
            int col = (c < 2) ? (p_j4 + 2 * c) : (60 + p_j4 + 2 * c);
            float4 v0, v1;
#pragma unroll
            for (int r = 0; r < 4; r++) {
                float lo, hi;
                up2(axw[r][c], lo, hi);
                if (r == 0) { v0.x = lo + c1v[2 * c]; v1.x = hi + c1v[2 * c + 1]; }
                else if (r == 1) { v0.y = lo + c1v[2 * c]; v1.y = hi + c1v[2 * c + 1]; }
                else if (r == 2) { v0.z = lo + c1v[2 * c]; v1.z = hi + c1v[2 * c + 1]; }
                else { v0.w = lo + c1v[2 * c]; v1.w = hi + c1v[2 * c + 1]; }
            }
            *reinterpret_cast<float4*>(xwg + col * 64 + p_i0)       = v0;
            *reinterpret_cast<float4*>(xwg + (col + 1) * 64 + p_i0) = v1;
        }
    }
    __syncthreads();
    // zero states, preload first A-panel
    for (int i = tid; i < 15232; i += NTHR) sm[i] = 0.f;
    for (int idx = tid; idx < 1280; idx += NTHR)
        *reinterpret_cast<float4*>(buf0 + idx * 4) = *reinterpret_cast<const float4*>(g_PA + idx * 4);
    __syncthreads();

    float* cur = buf0;
    float* oth = buf1;

    // ---- step loop: 11 slots (8 A + 2 B + 1 C) ----
    for (int s = 0; s < steps; s++) {
        float4 pr[5];

        // ---- loop A: h1 @ {-M1T, U1T, W2T} over 8 slots (K=16 each) ----
        ull aM1[8][2] = {}, aU1[8][2] = {}, aW2[8] = {};
#pragma unroll 1
        for (int p = 0; p < 8; p++) {
            const float* nx = (p < 7) ? (g_PA + (p + 1) * 5120) : g_PB;
            pld5(nx, tid, pr);
            gemmA(h1s + 16 * p * P, cur, i0, j4, j2, aM1, aU1, aW2);
            pst5(oth, tid, pr); __syncthreads();
            float* t = cur; cur = oth; oth = t;
        }

        // ---- update h1 (all h1s reads done at slot A7 barrier) ----
#pragma unroll
        for (int cp = 0; cp < 2; cp++) {
            int col = j4 + 2 * cp;
            float ub0 = sB[192 + col], ub1 = sB[192 + col + 1];
            float4 x0 = *reinterpret_cast<const float4*>(xwg + col * 64 + i0);
            float4 x1 = *reinterpret_cast<const float4*>(xwg + col * 64 + i0 + 4);
            float4 y0 = *reinterpret_cast<const float4*>(xwg + (col + 1) * 64 + i0);
            float4 y1 = *reinterpret_cast<const float4*>(xwg + (col + 1) * 64 + i0 + 4);
            float4 ha0 = *reinterpret_cast<float4*>(h1s + col * P + i0);
            float4 ha1 = *reinterpret_cast<float4*>(h1s + col * P + i0 + 4);
            float4 hb0 = *reinterpret_cast<float4*>(h1s + (col + 1) * P + i0);
            float4 hb1 = *reinterpret_cast<float4*>(h1s + (col + 1) * P + i0 + 4);
#pragma unroll
            for (int r = 0; r < 8; r++) {
                float m0, m1, u0, u1;
                up2(aM1[r][cp], m0, m1); up2(aU1[r][cp], u0, u1);
                float xw0 = (r < 4) ? ((r == 0) ? x0.x : (r == 1) ? x0.y : (r == 2) ? x0.z : x0.w)
                                    : ((r == 4) ? x1.x : (r == 5) ? x1.y : (r == 6) ? x1.z : x1.w);
                float xw1 = (r < 4) ? ((r == 0) ? y0.x : (r == 1) ? y0.y : (r == 2) ? y0.z : y0.w)
                                    : ((r == 4) ? y1.x : (r == 5) ? y1.y : (r == 6) ? y1.z : y1.w);
                float d0 = ftanh(xw0 + m0) + ftanh(u0 + ub0);
                float d1 = ftanh(xw1 + m1) + ftanh(u1 + ub1);
                if (r < 4) { addf4(ha0, r, d0); addf4(hb0, r, d1); }
                else       { addf4(ha1, r - 4, d0); addf4(hb1, r - 4, d1); }
            }
            *reinterpret_cast<float4*>(h1s + col * P + i0)           = ha0;
            *reinterpret_cast<float4*>(h1s + col * P + i0 + 4)       = ha1;
            *reinterpret_cast<float4*>(h1s + (col + 1) * P + i0)     = hb0;
            *reinterpret_cast<float4*>(h1s + (col + 1) * P + i0 + 4) = hb1;
        }

        // ---- loop B: h2 @ {-M2T, U2T, W3T} over 2 slots (K=32 each) ----
        ull aM2[8] = {}, aU2[8] = {}, aW3[8] = {};
#pragma unroll 1
        for (int q = 0; q < 2; q++) {
            const float* nx = (q < 1) ? (g_PB + 5120) : g_PC;
            pld5(nx, tid, pr);
            gemmB(h2s + 32 * q * P, cur, i0, j2, jc, aM2, aU2, aW3);
            pst5(oth, tid, pr); __syncthreads();
            float* t = cur; cur = oth; oth = t;
        }

        // ---- loop C: h3 @ {-M3T, U3T} (1 slot; stages next step's A0) ----
        ull aM3[8] = {}, aU3[8] = {};
        {
            pld5(g_PA, tid, pr);
            gemmC(h3s, cur, i0, jc, aM3, aU3);
            pst5(oth, tid, pr); __syncthreads();
            float* t = cur; cur = oth; oth = t;
        }

        // ---- update h3 (cq<16 owns; halves redundant in compute) ----
        if (cq < 16) {
            float cc0 = sB[jc], cc1 = sB[jc + 1];
            float ub0 = sB[32 + jc], ub1 = sB[32 + jc + 1];
            float4 ha0 = *reinterpret_cast<float4*>(h3s + jc * P + i0);
            float4 ha1 = *reinterpret_cast<float4*>(h3s + jc * P + i0 + 4);
            float4 hb0 = *reinterpret_cast<float4*>(h3s + (jc + 1) * P + i0);
            float4 hb1 = *reinterpret_cast<float4*>(h3s + (jc + 1) * P + i0 + 4);
#pragma unroll
            for (int r = 0; r < 8; r++) {
                float w0, w1, m0, m1, u0, u1;
                up2(aW3[r], w0, w1); up2(aM3[r], m0, m1); up2(aU3[r], u0, u1);
                float d0 = ftanh(w0 + m0 + cc0) + ftanh(u0 + ub0);
                float d1 = ftanh(w1 + m1 + cc1) + ftanh(u1 + ub1);
                if (r < 4) { addf4(ha0, r, d0); addf4(hb0, r, d1); }
                else       { addf4(ha1, r - 4, d0); addf4(hb1, r - 4, d1); }
            }
            *reinterpret_cast<float4*>(h3s + jc * P + i0)           = ha0;
            *reinterpret_cast<float4*>(h3s + jc * P + i0 + 4)       = ha1;
            *reinterpret_cast<float4*>(h3s + (jc + 1) * P + i0)     = hb0;
            *reinterpret_cast<float4*>(h3s + (jc + 1) * P + i0 + 4) = hb1;
        }

        // ---- update h2 ----
        {
            float cc0 = sB[64 + j2], cc1 = sB[64 + j2 + 1];
            float ub0 = sB[128 + j2], ub1 = sB[128 + j2 + 1];
            float4 ha0 = *reinterpret_cast<float4*>(h2s + j2 * P + i0);
            float4 ha1 = *reinterpret_cast<float4*>(h2s + j2 * P + i0 + 4);
            float4 hb0 = *reinterpret_cast<float4*>(h2s + (j2 + 1) * P + i0);
            float4 hb1 = *reinterpret_cast<float4*>(h2s + (j2 + 1) * P + i0 + 4);
#pragma unroll
            for (int r = 0; r < 8; r++) {
                float w0, w1, m0, m1, u0, u1;
                up2(aW2[r], w0, w1); up2(aM2[r], m0, m1); up2(aU2[r], u0, u1);
                float d0 = ftanh(w0 + m0 + cc0) + ftanh(u0 + ub0);
                float d1 = ftanh(w1 + m1 + cc1) + ftanh(u1 + ub1);
                if (r < 4) { addf4(ha0, r, d0); addf4(hb0, r, d1); }
                else       { addf4(ha1, r - 4, d0); addf4(hb1, r - 4, d1); }
            }
            *reinterpret_cast<float4*>(h2s + j2 * P + i0)           = ha0;
            *reinterpret_cast<float4*>(h2s + j2 * P + i0 + 4)       = ha1;
            *reinterpret_cast<float4*>(h2s + (j2 + 1) * P + i0)     = hb0;
            *reinterpret_cast<float4*>(h2s + (j2 + 1) * P + i0 + 4) = hb1;
        }
        // h2s/h3s updates are ordered before their next readers (loop B/C of the
        // next step) by the next step's A-slot barriers; h1s likewise by B/C bars.
    }
    __syncthreads();

    // ---- classifier: out = h3 @ clf^T + clf_b ----
    for (int idx = tid; idx < BT * 10; idx += NTHR) {
        int r = idx / 10, cc = idx - r * 10;
        float sacc = clfb[cc];
#pragma unroll
        for (int k = 0; k < 32; k++) sacc += h3s[k * P + r] * clfw[cc * 32 + k];
        out[(size_t)(row0 + r) * 10 + cc] = sacc;
    }
}

// ---------------- launch ----------------
extern "C" void kernel_launch(void* const* d_in, const int* in_sizes, int n_in,
                              void* d_out, int out_size) {
    const float* x    = (const float*)d_in[0];
    const float* W1w  = (const float*)d_in[1];
    const float* W1b  = (const float*)d_in[2];
    const float* U1w  = (const float*)d_in[3];
    const float* U1b  = (const float*)d_in[4];
    const float* W2w  = (const float*)d_in[5];
    const float* W2b  = (const float*)d_in[6];
    const float* U2w  = (const float*)d_in[7];
    const float* U2b  = (const float*)d_in[8];
    const float* W3w  = (const float*)d_in[9];
    const float* W3b  = (const float*)d_in[10];
    const float* U3w  = (const float*)d_in[11];
    const float* U3b  = (const float*)d_in[12];
    const float* fb3w = (const float*)d_in[13];
    const float* fb3b = (const float*)d_in[14];
    const float* fb2w = (const float*)d_in[15];
    const float* fb2b = (const float*)d_in[16];
    const float* fb1w = (const float*)d_in[17];
    const float* fb1b = (const float*)d_in[18];
    const float* clfw = (const float*)d_in[19];
    const float* clfb = (const float*)d_in[20];
    const int*   stp  = (const int*)d_in[21];

    int B = in_sizes[0] / 784;
    if (B > 65536) B = 65536;   // g_XW capacity guard

    prep_all<<<256, 128>>>(W1w, W1b, U1w, W2w, W2b, U2w, W3w, W3b, U3w,
                           fb3w, fb3b, fb2w, fb2b, fb1w, fb1b);

    const int smem_bytes = 25792 * 4;   // 103168 -> 2 CTAs/SM
    cudaFuncSetAttribute(pcnet_main, cudaFuncAttributeMaxDynamicSharedMemorySize, smem_bytes);
    pcnet_main<<<B / BT, NTHR, smem_bytes>>>(x, U1b, U2b, U3b, clfw, clfb, stp, (float*)d_out);
}